// round 11
// baseline (speedup 1.0000x reference)
#include <cuda_runtime.h>

#define NFEAT 8192
#define PDIM 256
#define RDIM 512
#define MROWS 32
#define NROWS 2048   // M*A
#define NSTACKS 32
#define NS 4
#define KSPLIT 4
#define KCHUNK (RDIM / KSPLIT)   // 128

#define BM 64
#define BN 64
#define BK 32

typedef unsigned long long ull;
typedef unsigned int uint;

// scratch (static device globals; no allocation in kernel_launch)
__device__ float g_proj4[KSPLIT * NROWS * PDIM];   // split-K partial projections
__device__ int   g_cnt[NS];
__device__ int   g_list[NS * NROWS];               // per-charge row segments
__device__ unsigned char g_dsign[NS * NSTACKS * 32]; // packed D sign bits per lane
__device__ float g_partial[NROWS * 4];             // 4 stack-groups per (m,a)

__device__ __forceinline__ ull pack2(float lo, float hi) {
    ull d;
    asm("mov.b64 %0, {%1, %2};" : "=l"(d) : "r"(__float_as_uint(lo)), "r"(__float_as_uint(hi)));
    return d;
}
__device__ __forceinline__ ull fma2(ull a, ull b, ull c) {
    ull d;
    asm("fma.rn.f32x2 %0, %1, %2, %3;" : "=l"(d) : "l"(a), "l"(b), "l"(c));
    return d;
}
__device__ __forceinline__ void unpack2(ull v, float& lo, float& hi) {
    unsigned int l, h;
    asm("mov.b64 {%0, %1}, %2;" : "=r"(l), "=r"(h) : "l"(v));
    lo = __uint_as_float(l); hi = __uint_as_float(h);
}

// First kernel: absorbs the DVFS ramp with useful prep.
// Block 0: classify rows by charge into per-charge segments (smem atomics).
// Block 1: pack D sign bits. List order within a charge is atomic-order
// dependent but only selects which GEMM tile handles which row; every row's
// arithmetic and output slot are fixed -> deterministic output.
__global__ void k_prep(const int* __restrict__ charges,
                       const float* __restrict__ Dmat) {
    int t = threadIdx.x;
    if (blockIdx.x == 0) {
        __shared__ int scnt[NS];
        if (t < NS) scnt[t] = 0;
        __syncthreads();
        for (int row = t; row < NROWS; row += 1024) {
            int s = charges[row];
            int pos = atomicAdd(&scnt[s], 1);
            g_list[s * NROWS + pos] = row;
        }
        __syncthreads();
        if (t < NS) g_cnt[t] = scnt[t];
    } else {
        // bit j of byte (s,st,lane) = signbit(D[s,st,lane*8+j])
        for (int i = t; i < NS * NSTACKS * 32; i += 1024) {
            int lane = i & 31;
            const float* dp = Dmat + (i >> 5) * PDIM + lane * 8;
            uint b = 0;
            #pragma unroll
            for (int j = 0; j < 8; j++)
                b |= (__float_as_uint(dp[j]) >> 31) << j;
            g_dsign[i] = (unsigned char)b;
        }
    }
}

// Charge-grouped split-K GEMM, 128 threads, 8x4 microtile (1.5 B LDS per FMA
// vs 2.0 for 4x4 -> ~25% less pressure on the binding smem crossbar).
// grid: (4 ntiles * 4 kslices, 32 row-blocks, 4 charges); dead row-blocks
// exit after a single LDG of g_cnt.
__global__ void __launch_bounds__(128)
k_gemm(const float* __restrict__ rep,
       const float* __restrict__ reductors) {
    int s = blockIdx.z;
    int cnt = g_cnt[s];
    int row0 = blockIdx.y * BM;
    if (row0 >= cnt) return;

    int ntile  = blockIdx.x & 3;
    int kslice = blockIdx.x >> 2;
    int k0 = kslice * KCHUNK;

    __shared__ __align__(16) float As[BK][BM];
    __shared__ __align__(16) float Bs[BK][BN];
    __shared__ int rowIdx[BM];

    int t = threadIdx.x;
    if (t < BM) {
        int gi = row0 + t;
        rowIdx[t] = (gi < cnt) ? g_list[s * NROWS + gi] : -1;
    }
    __syncthreads();

    int tx = t & 15;    // 16 col-groups of 4
    int ty = t >> 4;    // 8 row-groups of 8

    ull acc2[4][4] = {};   // acc2[jj][h] = rows (2h,2h+1) x col jj
    const float* redS = reductors + s * RDIM * PDIM + ntile * BN;

    for (int kb = k0; kb < k0 + KCHUNK; kb += BK) {
        // A tile: 512 float4 slots, 4 per thread (gathered rows)
        #pragma unroll
        for (int i = 0; i < 4; i++) {
            int slot = t * 4 + i;
            int r  = slot >> 3;
            int kq = slot & 7;
            int grow = rowIdx[r];
            float4 v = make_float4(0.f, 0.f, 0.f, 0.f);
            if (grow >= 0)
                v = *(const float4*)(rep + grow * RDIM + kb + kq * 4);
            As[kq * 4 + 0][r] = v.x;
            As[kq * 4 + 1][r] = v.y;
            As[kq * 4 + 2][r] = v.z;
            As[kq * 4 + 3][r] = v.w;
        }
        // B tile: 512 float4 slots, 4 per thread
        #pragma unroll
        for (int i = 0; i < 4; i++) {
            int slot = t * 4 + i;
            int k  = slot >> 4;
            int cq = slot & 15;
            float4 v = *(const float4*)(redS + (kb + k) * PDIM + cq * 4);
            *(float4*)&Bs[k][cq * 4] = v;
        }
        __syncthreads();

        #pragma unroll
        for (int k = 0; k < BK; k++) {
            float4 alo = *(const float4*)&As[k][ty * 8];
            float4 ahi = *(const float4*)&As[k][ty * 8 + 4];
            float4 b4  = *(const float4*)&Bs[k][tx * 4];
            ull a01 = pack2(alo.x, alo.y);
            ull a23 = pack2(alo.z, alo.w);
            ull a45 = pack2(ahi.x, ahi.y);
            ull a67 = pack2(ahi.z, ahi.w);
            float bv[4] = {b4.x, b4.y, b4.z, b4.w};
            #pragma unroll
            for (int jj = 0; jj < 4; jj++) {
                ull bd = pack2(bv[jj], bv[jj]);
                acc2[jj][0] = fma2(a01, bd, acc2[jj][0]);
                acc2[jj][1] = fma2(a23, bd, acc2[jj][1]);
                acc2[jj][2] = fma2(a45, bd, acc2[jj][2]);
                acc2[jj][3] = fma2(a67, bd, acc2[jj][3]);
            }
        }
        __syncthreads();
    }

    float acc[8][4];
    #pragma unroll
    for (int jj = 0; jj < 4; jj++) {
        unpack2(acc2[jj][0], acc[0][jj], acc[1][jj]);
        unpack2(acc2[jj][1], acc[2][jj], acc[3][jj]);
        unpack2(acc2[jj][2], acc[4][jj], acc[5][jj]);
        unpack2(acc2[jj][3], acc[6][jj], acc[7][jj]);
    }

    float* outSlice = g_proj4 + kslice * (NROWS * PDIM);
    #pragma unroll
    for (int ii = 0; ii < 8; ii++) {
        int r = rowIdx[ty * 8 + ii];
        if (r >= 0) {
            float4 v = make_float4(acc[ii][0], acc[ii][1], acc[ii][2], acc[ii][3]);
            *(float4*)(outSlice + r * PDIM + ntile * BN + tx * 4) = v;
        }
    }
}

// One warp per (pair, stack-group): 8192 tasks. FWHT-256 with half-exchange
// lane stages: element (lane q, reg r) ends at logical index
// 128*(r>>2) + (q>>1)*8 + (q&1)*4 + (r&3); bias/alpha load at the matching
// permuted bases (two contiguous float4 runs; alpha-dot is permutation
// invariant). D signs come from the packed byte table (1-byte load replaces
// 32 B/lane of Dmat traffic). No fences, no fused reduce (R6/R7 lesson:
// gpu-scope fence emits CCTL.IVALL and poisons L1 for co-resident blocks).
__global__ void __launch_bounds__(256)
k_feat(const int* __restrict__ charges,
       const float* __restrict__ bias,
       const float* __restrict__ alpha) {
    int warpId = threadIdx.x >> 5;
    int lane   = threadIdx.x & 31;
    int task   = blockIdx.x * 8 + warpId;   // 0..8191
    int pair   = task >> 2;
    int grp    = task & 3;
    int st0    = grp * 8;

    int s = charges[pair];

    uint projb[8];
    {
        const float* pp = g_proj4 + pair * PDIM + lane * 8;
        float4 p0 = *(const float4*)pp;
        float4 p1 = *(const float4*)(pp + 4);
        float acc[8] = {p0.x, p0.y, p0.z, p0.w, p1.x, p1.y, p1.z, p1.w};
        #pragma unroll
        for (int c = 1; c < KSPLIT; c++) {
            const float* pc = g_proj4 + c * (NROWS * PDIM) + pair * PDIM + lane * 8;
            float4 q0 = *(const float4*)pc;
            float4 q1 = *(const float4*)(pc + 4);
            acc[0] += q0.x; acc[1] += q0.y; acc[2] += q0.z; acc[3] += q0.w;
            acc[4] += q1.x; acc[5] += q1.y; acc[6] += q1.z; acc[7] += q1.w;
        }
        // fold FWHT normalization 1/16 (COEFF_NORM == 1 exactly)
        #pragma unroll
        for (int j = 0; j < 8; j++) projb[j] = __float_as_uint(acc[j] * 0.0625f);
    }

    const unsigned char* ds = g_dsign + s * NSTACKS * 32 + lane;
    const float* bs = bias + s * NFEAT;
    int pbase = ((lane >> 1) << 3) + ((lane & 1) << 2);

    float sum = 0.f;
    for (int st = st0; st < st0 + 8; st++) {
        uint dbyte = ds[st * 32];
        float v[8];
        #pragma unroll
        for (int j = 0; j < 8; j++)
            v[j] = __uint_as_float(projb[j] ^ ((dbyte << (31 - j)) & 0x80000000u));

        float tv;
        tv = v[0]; v[0] = tv + v[1]; v[1] = tv - v[1];
        tv = v[2]; v[2] = tv + v[3]; v[3] = tv - v[3];
        tv = v[4]; v[4] = tv + v[5]; v[5] = tv - v[5];
        tv = v[6]; v[6] = tv + v[7]; v[7] = tv - v[7];

        tv = v[0]; v[0] = tv + v[2]; v[2] = tv - v[2];
        tv = v[1]; v[1] = tv + v[3]; v[3] = tv - v[3];
        tv = v[4]; v[4] = tv + v[6]; v[6] = tv - v[6];
        tv = v[5]; v[5] = tv + v[7]; v[7] = tv - v[7];

        tv = v[0]; v[0] = tv + v[4]; v[4] = tv - v[4];
        tv = v[1]; v[1] = tv + v[5]; v[5] = tv - v[5];
        tv = v[2]; v[2] = tv + v[6]; v[6] = tv - v[6];
        tv = v[3]; v[3] = tv + v[7]; v[7] = tv - v[7];

        #pragma unroll
        for (int msk = 1; msk <= 16; msk <<= 1) {
            bool hi = (lane & msk) != 0;
            float sgn = hi ? -1.f : 1.f;
            float nv[8];
            #pragma unroll
            for (int r = 0; r < 4; r++) {
                float send = hi ? v[r]     : v[r + 4];
                float keep = hi ? v[r + 4] : v[r];
                float recv = __shfl_xor_sync(0xffffffffu, send, msk);
                nv[r]     = keep + recv;
                nv[r + 4] = (keep - recv) * sgn;
            }
            #pragma unroll
            for (int r = 0; r < 8; r++) v[r] = nv[r];
        }

        const float* bp = bs + st * PDIM + pbase;
        const float* ap = alpha + st * PDIM + pbase;
        float4 b0 = *(const float4*)bp;
        float4 b1 = *(const float4*)(bp + 128);
        float4 a0 = *(const float4*)ap;
        float4 a1 = *(const float4*)(ap + 128);
        float bb[8] = {b0.x, b0.y, b0.z, b0.w, b1.x, b1.y, b1.z, b1.w};
        float aa[8] = {a0.x, a0.y, a0.z, a0.w, a1.x, a1.y, a1.z, a1.w};
        #pragma unroll
        for (int j = 0; j < 8; j++)
            sum += __cosf(v[j] + bb[j]) * aa[j];
    }

    #pragma unroll
    for (int off = 16; off; off >>= 1)
        sum += __shfl_down_sync(0xffffffffu, sum, off);
    if (lane == 0) g_partial[task] = sum;   // task = m*256 + a*4 + grp
}

// out[m] = FEAT_NORM * sum over 256 contiguous partials
__global__ void k_reduce(float* __restrict__ out) {
    int m = blockIdx.x;
    int t = threadIdx.x;   // 256 threads
    float v = g_partial[m * 256 + t];
    #pragma unroll
    for (int off = 16; off; off >>= 1)
        v += __shfl_down_sync(0xffffffffu, v, off);
    __shared__ float sm8[8];
    if ((t & 31) == 0) sm8[t >> 5] = v;
    __syncthreads();
    if (t < 8) {
        float w = sm8[t];
        #pragma unroll
        for (int off = 4; off; off >>= 1)
            w += __shfl_down_sync(0xffu, w, off);
        if (t == 0) out[m] = 0.015625f * w;   // FEAT_NORM = 1/64
    }
}

extern "C" void kernel_launch(void* const* d_in, const int* in_sizes, int n_in,
                              void* d_out, int out_size) {
    const float* rep       = (const float*)d_in[0];
    const int*   charges   = (const int*)d_in[1];
    const float* reductors = (const float*)d_in[2];
    const float* Dmat      = (const float*)d_in[3];
    const float* bias      = (const float*)d_in[4];
    const float* alpha     = (const float*)d_in[5];
    float* out = (float*)d_out;

    k_prep<<<2, 1024>>>(charges, Dmat);
    dim3 gg(4 * KSPLIT, NROWS / BM, NS);   // (16, 32, 4); dead row-blocks exit fast
    k_gemm<<<gg, 128>>>(rep, reductors);
    k_feat<<<1024, 256>>>(charges, bias, alpha);   // 8192 warps
    k_reduce<<<MROWS, 256>>>(out);
}

// round 12
// speedup vs baseline: 1.1659x; 1.1659x over previous
#include <cuda_runtime.h>

#define NFEAT 8192
#define PDIM 256
#define RDIM 512
#define MROWS 32
#define NROWS 2048   // M*A
#define NSTACKS 32
#define NS 4
#define KSPLIT 4
#define KCHUNK (RDIM / KSPLIT)   // 128

#define BM 64
#define BN 64
#define BK 32

typedef unsigned long long ull;
typedef unsigned int uint;

// scratch (static device globals; no allocation in kernel_launch)
__device__ float g_proj4[KSPLIT * NROWS * PDIM];   // split-K partial projections
__device__ int   g_cnt[NS];
__device__ int   g_list[NS * NROWS];
__device__ float g_partial[NROWS * 4];             // 4 stack-groups per (m,a)

__device__ __forceinline__ ull pack2(float lo, float hi) {
    ull d;
    asm("mov.b64 %0, {%1, %2};" : "=l"(d) : "r"(__float_as_uint(lo)), "r"(__float_as_uint(hi)));
    return d;
}
__device__ __forceinline__ ull fma2(ull a, ull b, ull c) {
    ull d;
    asm("fma.rn.f32x2 %0, %1, %2, %3;" : "=l"(d) : "l"(a), "l"(b), "l"(c));
    return d;
}
__device__ __forceinline__ void unpack2(ull v, float& lo, float& hi) {
    unsigned int l, h;
    asm("mov.b64 {%0, %1}, %2;" : "=r"(l), "=r"(h) : "l"(v));
    lo = __uint_as_float(l); hi = __uint_as_float(h);
}

// fused init + classify: one block, smem counters (absorbs the DVFS ramp).
// List order is atomic-order dependent but only selects which GEMM tile
// handles which row; each row's arithmetic and output slot are fixed, so
// final output bits are deterministic.
__global__ void k_classify(const int* __restrict__ charges) {
    __shared__ int scnt[NS];
    int t = threadIdx.x;
    if (t < NS) scnt[t] = 0;
    __syncthreads();
    for (int row = t; row < NROWS; row += 1024) {
        int s = charges[row];
        int pos = atomicAdd(&scnt[s], 1);
        g_list[s * NROWS + pos] = row;
    }
    __syncthreads();
    if (t < NS) g_cnt[t] = scnt[t];
}

// Charge-grouped split-K GEMM, 256 threads, 4x4 microtile (champion shape),
// with software-pipelined global loads: next tile's LDGs issue before the
// current tile's FMA loop, hiding L2 latency behind 512 FFMA2s.
__global__ void __launch_bounds__(256)
k_gemm(const float* __restrict__ rep,
       const float* __restrict__ reductors) {
    int s = blockIdx.z;
    int cnt = g_cnt[s];
    int row0 = blockIdx.y * BM;
    if (row0 >= cnt) return;

    int ntile  = blockIdx.x & 3;
    int kslice = blockIdx.x >> 2;
    int k0 = kslice * KCHUNK;

    __shared__ __align__(16) float As[BK][BM];
    __shared__ __align__(16) float Bs[BK][BN];
    __shared__ int rowIdx[BM];

    int t  = threadIdx.x;
    int tx = t & 15;
    int ty = t >> 4;

    if (t < BM) {
        int gi = row0 + t;
        rowIdx[t] = (gi < cnt) ? g_list[s * NROWS + gi] : -1;
    }
    __syncthreads();

    const float* redS = reductors + s * RDIM * PDIM + ntile * BN;

    // per-thread slot decompositions (2 slots each for A and B)
    int slot0 = t * 2, slot1 = t * 2 + 1;
    int ar0 = slot0 >> 3, ak0 = slot0 & 7;
    int ar1 = slot1 >> 3, ak1 = slot1 & 7;
    int bk0 = slot0 >> 4, bc0 = slot0 & 15;
    int bk1 = slot1 >> 4, bc1 = slot1 & 15;
    int grow0 = rowIdx[ar0];
    int grow1 = rowIdx[ar1];

    float4 va0, va1, vb0, vb1;
    {   // prologue loads for kb = k0
        va0 = make_float4(0.f, 0.f, 0.f, 0.f);
        va1 = va0;
        if (grow0 >= 0) va0 = *(const float4*)(rep + grow0 * RDIM + k0 + ak0 * 4);
        if (grow1 >= 0) va1 = *(const float4*)(rep + grow1 * RDIM + k0 + ak1 * 4);
        vb0 = *(const float4*)(redS + (k0 + bk0) * PDIM + bc0 * 4);
        vb1 = *(const float4*)(redS + (k0 + bk1) * PDIM + bc1 * 4);
    }

    ull acc2[4][2] = {};

    for (int kb = k0; kb < k0 + KCHUNK; kb += BK) {
        // store current tile to smem
        As[ak0 * 4 + 0][ar0] = va0.x;
        As[ak0 * 4 + 1][ar0] = va0.y;
        As[ak0 * 4 + 2][ar0] = va0.z;
        As[ak0 * 4 + 3][ar0] = va0.w;
        As[ak1 * 4 + 0][ar1] = va1.x;
        As[ak1 * 4 + 1][ar1] = va1.y;
        As[ak1 * 4 + 2][ar1] = va1.z;
        As[ak1 * 4 + 3][ar1] = va1.w;
        *(float4*)&Bs[bk0][bc0 * 4] = vb0;
        *(float4*)&Bs[bk1][bc1 * 4] = vb1;
        __syncthreads();

        // issue next tile's loads (overlap with FMA below)
        int kn = kb + BK;
        if (kn < k0 + KCHUNK) {
            va0 = make_float4(0.f, 0.f, 0.f, 0.f);
            va1 = va0;
            if (grow0 >= 0) va0 = *(const float4*)(rep + grow0 * RDIM + kn + ak0 * 4);
            if (grow1 >= 0) va1 = *(const float4*)(rep + grow1 * RDIM + kn + ak1 * 4);
            vb0 = *(const float4*)(redS + (kn + bk0) * PDIM + bc0 * 4);
            vb1 = *(const float4*)(redS + (kn + bk1) * PDIM + bc1 * 4);
        }

        #pragma unroll
        for (int k = 0; k < BK; k++) {
            float4 a4 = *(const float4*)&As[k][ty * 4];
            float4 b4 = *(const float4*)&Bs[k][tx * 4];
            ull a01 = pack2(a4.x, a4.y);
            ull a23 = pack2(a4.z, a4.w);
            float bv[4] = {b4.x, b4.y, b4.z, b4.w};
            #pragma unroll
            for (int jj = 0; jj < 4; jj++) {
                ull bd = pack2(bv[jj], bv[jj]);
                acc2[jj][0] = fma2(a01, bd, acc2[jj][0]);
                acc2[jj][1] = fma2(a23, bd, acc2[jj][1]);
            }
        }
        __syncthreads();
    }

    float acc[4][4];
    #pragma unroll
    for (int jj = 0; jj < 4; jj++) {
        unpack2(acc2[jj][0], acc[0][jj], acc[1][jj]);
        unpack2(acc2[jj][1], acc[2][jj], acc[3][jj]);
    }

    float* outSlice = g_proj4 + kslice * (NROWS * PDIM);
    #pragma unroll
    for (int ii = 0; ii < 4; ii++) {
        int r = rowIdx[ty * 4 + ii];
        if (r >= 0) {
            float4 v = make_float4(acc[ii][0], acc[ii][1], acc[ii][2], acc[ii][3]);
            *(float4*)(outSlice + r * PDIM + ntile * BN + tx * 4) = v;
        }
    }
}

// One warp per (pair, stack-group): 8192 tasks. FWHT-256 with half-exchange
// lane stages: element (lane q, reg r) ends at logical index
// 128*(r>>2) + (q>>1)*8 + (q&1)*4 + (r&3); bias/alpha load at the matching
// permuted bases (two contiguous float4 runs; alpha-dot is permutation
// invariant). Champion shape; only delta: predicated-subtract instead of
// (keep-recv)*sgn, removing 4 FMULs per lane stage.
__global__ void __launch_bounds__(256)
k_feat(const int* __restrict__ charges,
       const float* __restrict__ Dmat,
       const float* __restrict__ bias,
       const float* __restrict__ alpha) {
    int warpId = threadIdx.x >> 5;
    int lane   = threadIdx.x & 31;
    int task   = blockIdx.x * 8 + warpId;   // 0..8191
    int pair   = task >> 2;
    int grp    = task & 3;
    int st0    = grp * 8;

    int s = charges[pair];

    uint projb[8];
    {
        const float* pp = g_proj4 + pair * PDIM + lane * 8;
        float4 p0 = *(const float4*)pp;
        float4 p1 = *(const float4*)(pp + 4);
        float acc[8] = {p0.x, p0.y, p0.z, p0.w, p1.x, p1.y, p1.z, p1.w};
        #pragma unroll
        for (int c = 1; c < KSPLIT; c++) {
            const float* pc = g_proj4 + c * (NROWS * PDIM) + pair * PDIM + lane * 8;
            float4 q0 = *(const float4*)pc;
            float4 q1 = *(const float4*)(pc + 4);
            acc[0] += q0.x; acc[1] += q0.y; acc[2] += q0.z; acc[3] += q0.w;
            acc[4] += q1.x; acc[5] += q1.y; acc[6] += q1.z; acc[7] += q1.w;
        }
        // fold FWHT normalization 1/16 (COEFF_NORM == 1 exactly)
        #pragma unroll
        for (int j = 0; j < 8; j++) projb[j] = __float_as_uint(acc[j] * 0.0625f);
    }

    const float* Ds = Dmat + s * NSTACKS * PDIM;
    const float* bs = bias + s * NFEAT;
    int pbase = ((lane >> 1) << 3) + ((lane & 1) << 2);

    float sum = 0.f;
    for (int st = st0; st < st0 + 8; st++) {
        const uint4* dp = (const uint4*)(Ds + st * PDIM + lane * 8);
        uint4 d0 = dp[0];
        uint4 d1 = dp[1];
        uint db[8] = {d0.x, d0.y, d0.z, d0.w, d1.x, d1.y, d1.z, d1.w};
        float v[8];
        #pragma unroll
        for (int j = 0; j < 8; j++)
            v[j] = __uint_as_float(projb[j] ^ (db[j] & 0x80000000u));

        float tv;
        tv = v[0]; v[0] = tv + v[1]; v[1] = tv - v[1];
        tv = v[2]; v[2] = tv + v[3]; v[3] = tv - v[3];
        tv = v[4]; v[4] = tv + v[5]; v[5] = tv - v[5];
        tv = v[6]; v[6] = tv + v[7]; v[7] = tv - v[7];

        tv = v[0]; v[0] = tv + v[2]; v[2] = tv - v[2];
        tv = v[1]; v[1] = tv + v[3]; v[3] = tv - v[3];
        tv = v[4]; v[4] = tv + v[6]; v[6] = tv - v[6];
        tv = v[5]; v[5] = tv + v[7]; v[7] = tv - v[7];

        tv = v[0]; v[0] = tv + v[4]; v[4] = tv - v[4];
        tv = v[1]; v[1] = tv + v[5]; v[5] = tv - v[5];
        tv = v[2]; v[2] = tv + v[6]; v[6] = tv - v[6];
        tv = v[3]; v[3] = tv + v[7]; v[7] = tv - v[7];

        #pragma unroll
        for (int msk = 1; msk <= 16; msk <<= 1) {
            bool hi = (lane & msk) != 0;
            float nv[8];
            #pragma unroll
            for (int r = 0; r < 4; r++) {
                float send = hi ? v[r]     : v[r + 4];
                float keep = hi ? v[r + 4] : v[r];
                float recv = __shfl_xor_sync(0xffffffffu, send, msk);
                nv[r]     = keep + recv;
                nv[r + 4] = hi ? (recv - keep) : (keep - recv);  // no FMUL
            }
            #pragma unroll
            for (int r = 0; r < 8; r++) v[r] = nv[r];
        }

        const float* bp = bs + st * PDIM + pbase;
        const float* ap = alpha + st * PDIM + pbase;
        float4 b0 = *(const float4*)bp;
        float4 b1 = *(const float4*)(bp + 128);
        float4 a0 = *(const float4*)ap;
        float4 a1 = *(const float4*)(ap + 128);
        float bb[8] = {b0.x, b0.y, b0.z, b0.w, b1.x, b1.y, b1.z, b1.w};
        float aa[8] = {a0.x, a0.y, a0.z, a0.w, a1.x, a1.y, a1.z, a1.w};
        #pragma unroll
        for (int j = 0; j < 8; j++)
            sum += __cosf(v[j] + bb[j]) * aa[j];
    }

    #pragma unroll
    for (int off = 16; off; off >>= 1)
        sum += __shfl_down_sync(0xffffffffu, sum, off);
    if (lane == 0) g_partial[task] = sum;   // task = m*256 + a*4 + grp
}

// out[m] = FEAT_NORM * sum over 256 contiguous partials
__global__ void k_reduce(float* __restrict__ out) {
    int m = blockIdx.x;
    int t = threadIdx.x;   // 256 threads
    float v = g_partial[m * 256 + t];
    #pragma unroll
    for (int off = 16; off; off >>= 1)
        v += __shfl_down_sync(0xffffffffu, v, off);
    __shared__ float sm8[8];
    if ((t & 31) == 0) sm8[t >> 5] = v;
    __syncthreads();
    if (t < 8) {
        float w = sm8[t];
        #pragma unroll
        for (int off = 4; off; off >>= 1)
            w += __shfl_down_sync(0xffu, w, off);
        if (t == 0) out[m] = 0.015625f * w;   // FEAT_NORM = 1/64
    }
}

extern "C" void kernel_launch(void* const* d_in, const int* in_sizes, int n_in,
                              void* d_out, int out_size) {
    const float* rep       = (const float*)d_in[0];
    const int*   charges   = (const int*)d_in[1];
    const float* reductors = (const float*)d_in[2];
    const float* Dmat      = (const float*)d_in[3];
    const float* bias      = (const float*)d_in[4];
    const float* alpha     = (const float*)d_in[5];
    float* out = (float*)d_out;

    k_classify<<<1, 1024>>>(charges);
    dim3 gg(4 * KSPLIT, NROWS / BM, NS);   // (16, 32, 4); dead row-blocks exit fast
    k_gemm<<<gg, 256>>>(rep, reductors);
    k_feat<<<1024, 256>>>(charges, Dmat, bias, alpha);   // 8192 warps
    k_reduce<<<MROWS, 256>>>(out);
}